// round 5
// baseline (speedup 1.0000x reference)
#include <cuda_runtime.h>
#include <cuda_bf16.h>
#include <cstdint>

// Problem constants
#define BB 4
#define SS 4096
#define DD 128

// bf16 hi/lo split Q,K,V (scale folded into Q). 4 MB each.
__device__ __nv_bfloat16 g_Qh[BB * SS * DD];
__device__ __nv_bfloat16 g_Ql[BB * SS * DD];
__device__ __nv_bfloat16 g_Kh[BB * SS * DD];
__device__ __nv_bfloat16 g_Kl[BB * SS * DD];
__device__ __nv_bfloat16 g_Vh[BB * SS * DD];
__device__ __nv_bfloat16 g_Vl[BB * SS * DD];

// ---------------------------------------------------------------------------
// shared helpers
// ---------------------------------------------------------------------------
__device__ __forceinline__ void ldsm_x4(uint32_t r[4], uint32_t addr) {
    asm volatile("ldmatrix.sync.aligned.m8n8.x4.shared.b16 {%0,%1,%2,%3}, [%4];"
                 : "=r"(r[0]), "=r"(r[1]), "=r"(r[2]), "=r"(r[3]) : "r"(addr));
}
__device__ __forceinline__ void ldsm_x4t(uint32_t r[4], uint32_t addr) {
    asm volatile("ldmatrix.sync.aligned.m8n8.x4.trans.shared.b16 {%0,%1,%2,%3}, [%4];"
                 : "=r"(r[0]), "=r"(r[1]), "=r"(r[2]), "=r"(r[3]) : "r"(addr));
}
__device__ __forceinline__ void mma_bf16(float c[4], const uint32_t a[4],
                                         const uint32_t b[2]) {
    asm volatile(
        "mma.sync.aligned.m16n8k16.row.col.f32.bf16.bf16.f32 "
        "{%0,%1,%2,%3}, {%4,%5,%6,%7}, {%8,%9}, {%0,%1,%2,%3};"
        : "+f"(c[0]), "+f"(c[1]), "+f"(c[2]), "+f"(c[3])
        : "r"(a[0]), "r"(a[1]), "r"(a[2]), "r"(a[3]), "r"(b[0]), "r"(b[1]));
}
// pack (x0,x1) -> bf16x2 hi-part, and residual lo-part
__device__ __forceinline__ void split_pack(float x0, float x1,
                                           uint32_t& hp, uint32_t& lp) {
    asm("cvt.rn.bf16x2.f32 %0, %1, %2;" : "=r"(hp) : "f"(x1), "f"(x0));
    float h0 = __uint_as_float(hp << 16);
    float h1 = __uint_as_float(hp & 0xffff0000u);
    asm("cvt.rn.bf16x2.f32 %0, %1, %2;" : "=r"(lp) : "f"(x1 - h1), "f"(x0 - h0));
}
__device__ __forceinline__ void cp16(uint32_t dst, const void* src) {
    asm volatile("cp.async.cg.shared.global [%0], [%1], 16;" :: "r"(dst), "l"(src));
}

// ---------------------------------------------------------------------------
// Kernel 1: QKV projection via mma.sync bf16 2-way split.
//   y = x @ W^T (Q scaled by 1/sqrt(128)), outputs split bf16 hi/lo.
// Grid (128, 3), 256 threads (8 warps). Warp w owns out rows w*16..+15.
// smem: sXh/sXl [128][136] + sWh/sWl [128][136] bf16 = 139264 B.
// ---------------------------------------------------------------------------
#define W_HALF (128 * 136)
#define QKV_SMEM (4 * W_HALF * 2)

__global__ __launch_bounds__(256) void qkv_kernel(const float* __restrict__ x,
                                                  const float* __restrict__ Wq,
                                                  const float* __restrict__ Wk,
                                                  const float* __restrict__ Wv) {
    extern __shared__ __nv_bfloat16 qsm[];
    __nv_bfloat16* sXh = qsm;
    __nv_bfloat16* sXl = qsm + W_HALF;
    __nv_bfloat16* sWh = qsm + 2 * W_HALF;
    __nv_bfloat16* sWl = qsm + 3 * W_HALF;

    const uint32_t uB  = (uint32_t)__cvta_generic_to_shared(qsm);
    const uint32_t uXh = uB;
    const uint32_t uXl = uB + W_HALF * 2;
    const uint32_t uWh = uB + 2 * W_HALF * 2;

    const int w = blockIdx.y;
    const float* W = (w == 0) ? Wq : (w == 1) ? Wk : Wv;
    __nv_bfloat16* oh = (w == 0) ? g_Qh : (w == 1) ? g_Kh : g_Vh;
    __nv_bfloat16* ol = (w == 0) ? g_Ql : (w == 1) ? g_Kl : g_Vl;
    const float sc = (w == 0) ? 0.08838834764831845f : 1.0f;

    const int row0 = blockIdx.x * 128;
    const int tid = threadIdx.x;
    const int warp = tid >> 5;
    const int lane = tid & 31;

    // ---- load + convert x tile and W into split bf16 smem ----
    {
        const float4* xg = (const float4*)(x + (size_t)row0 * DD);
        const float4* wg = (const float4*)W;
        for (int t = tid; t < 4096; t += 256) {
            int r = t >> 5;
            int c = (t & 31) * 4;
            float4 xv = xg[t];
            uint32_t h0, l0, h1, l1;
            split_pack(xv.x, xv.y, h0, l0);
            split_pack(xv.z, xv.w, h1, l1);
            *(uint2*)(sXh + r * 136 + c) = make_uint2(h0, h1);
            *(uint2*)(sXl + r * 136 + c) = make_uint2(l0, l1);
            float4 wv = wg[t];
            split_pack(wv.x, wv.y, h0, l0);
            split_pack(wv.z, wv.w, h1, l1);
            *(uint2*)(sWh + r * 136 + c) = make_uint2(h0, h1);
            *(uint2*)(sWl + r * 136 + c) = make_uint2(l0, l1);
        }
    }
    __syncthreads();

    // per-lane ldmatrix offsets
    const uint32_t aoff = (uint32_t)(((warp * 16 + (lane & 15)) * 136 +
                                      ((lane >> 4) << 3)) * 2);
    const uint32_t boff = (uint32_t)(((lane & 7) * 136 +
                                      (((lane >> 3) & 1) << 3)) * 2) +
                          ((lane >> 4) ? (uint32_t)(W_HALF * 2) : 0u);

    float o[16][4];
#pragma unroll
    for (int nt = 0; nt < 16; nt++)
#pragma unroll
        for (int k = 0; k < 4; k++) o[nt][k] = 0.0f;

#pragma unroll
    for (int ks = 0; ks < 8; ks++) {
        uint32_t qa[4], ql[4];
        ldsm_x4(qa, uXh + aoff + ks * 32);
        ldsm_x4(ql, uXl + aoff + ks * 32);
#pragma unroll
        for (int nt = 0; nt < 16; nt++) {
            uint32_t kk[4];   // [0,1]=Whi, [2,3]=Wlo
            ldsm_x4(kk, uWh + boff + (uint32_t)(nt * 8 * 136 * 2 + ks * 32));
            mma_bf16(o[nt], qa, kk);
            mma_bf16(o[nt], qa, kk + 2);
            mma_bf16(o[nt], ql, kk);
        }
    }

    // ---- epilogue: scale, split, store ----
    const int r0 = row0 + warp * 16 + (lane >> 2);
    const int cc = (lane & 3) * 2;
#pragma unroll
    for (int nt = 0; nt < 16; nt++) {
        uint32_t hp, lp;
        split_pack(o[nt][0] * sc, o[nt][1] * sc, hp, lp);
        *(uint32_t*)(oh + (size_t)r0 * DD + nt * 8 + cc) = hp;
        *(uint32_t*)(ol + (size_t)r0 * DD + nt * 8 + cc) = lp;
        split_pack(o[nt][2] * sc, o[nt][3] * sc, hp, lp);
        *(uint32_t*)(oh + (size_t)(r0 + 8) * DD + nt * 8 + cc) = hp;
        *(uint32_t*)(ol + (size_t)(r0 + 8) * DD + nt * 8 + cc) = lp;
    }
}

// ---------------------------------------------------------------------------
// Kernel 2: causal flash attention, mma.sync bf16 2-way split, 16 warps/CTA.
// Warp w: q-row group wg=w&3 (rows wg*16..+15), key quarter h=w>>2
// (keys h*16..+15 of each 64-key tile). Independent online softmax per
// quarter; 4-way merge once per pass via smem. CTA x -> q-tiles {x, 63-x}.
// K/V double-buffered cp.async; hi/lo ldmatrix fused (lanes 16-31 -> lo).
// ---------------------------------------------------------------------------
#define T_HALF 8704
#define ATTN_SMEM (10 * T_HALF * 2)      // 174080 B

__global__ __launch_bounds__(512, 1) void attn_kernel(float* __restrict__ out) {
    extern __shared__ __nv_bfloat16 smh[];

    const uint32_t uB  = (uint32_t)__cvta_generic_to_shared(smh);
    const uint32_t uQh = uB;
    const uint32_t uQl = uB + T_HALF * 2;
    const uint32_t uKV = uB + 2 * T_HALF * 2;      // stage s at uKV + s*4T*2

    __nv_bfloat16* sQh = smh;
    __nv_bfloat16* sQl = smh + T_HALF;
    // epilogue merge buffers overlay the whole KV region (both stages):
    // 3 O-buffers [64][132] + 3x m[64] + 3x l[64] = 102912 B < 139264 B.
    float* OB = (float*)(smh + 2 * T_HALF);
    float* mB = OB + 3 * 64 * 132;
    float* lB = mB + 3 * 64;

    const int b = blockIdx.y;
    const int tid = threadIdx.x;
    const int warp = tid >> 5;
    const int lane = tid & 31;
    const int wg = warp & 3;          // q-row group
    const int h = warp >> 2;          // key quarter (16 keys each)

    // ldmatrix per-lane offsets (bytes)
    const uint32_t qoff = (uint32_t)(((wg * 16 + (lane & 15)) * 136 +
                                      ((lane >> 4) << 3)) * 2);
    const uint32_t koff0 = (uint32_t)(((h * 16 + (lane & 7)) * 136 +
                                       (((lane >> 3) & 1) << 3)) * 2);
    const uint32_t voff0 = (uint32_t)((h * 16 + (lane & 15)) * 136 * 2);
    const uint32_t loSel = (lane >> 4) ? (uint32_t)(T_HALF * 2) : 0u;

    const float NEG = -1e30f;

    for (int pass = 0; pass < 2; pass++) {
        const int iq = pass ? (63 - blockIdx.x) : blockIdx.x;
        __syncthreads();   // previous pass fully done (incl. epilogue reads)

        // ---- load Q tile (hi/lo): 1024 uint4 each ----
        {
            const uint4* QH = (const uint4*)(g_Qh + ((size_t)b * SS + iq * 64) * DD);
            const uint4* QL = (const uint4*)(g_Ql + ((size_t)b * SS + iq * 64) * DD);
#pragma unroll
            for (int i = 0; i < 2; i++) {
                int idx = tid + i * 512;
                int r = idx >> 4, c = idx & 15;
                *(uint4*)(sQh + r * 136 + c * 8) = QH[idx];
                *(uint4*)(sQl + r * 136 + c * 8) = QL[idx];
            }
        }

        // ---- prefetch K/V tile 0 into stage 0 ----
        {
            const size_t goff = ((size_t)b * SS) * DD;
            const uint4* srcs[4] = {(const uint4*)(g_Kh + goff), (const uint4*)(g_Kl + goff),
                                    (const uint4*)(g_Vh + goff), (const uint4*)(g_Vl + goff)};
#pragma unroll
            for (int a = 0; a < 4; a++)
#pragma unroll
                for (int i = 0; i < 2; i++) {
                    int idx = tid + i * 512;
                    int r = idx >> 4, c = idx & 15;
                    cp16(uKV + (uint32_t)(a * T_HALF * 2 + (r * 136 + c * 8) * 2),
                         srcs[a] + idx);
                }
            asm volatile("cp.async.commit_group;");
        }

        float o[16][4];
#pragma unroll
        for (int nd = 0; nd < 16; nd++)
#pragma unroll
            for (int k = 0; k < 4; k++) o[nd][k] = 0.0f;
        float mr0 = NEG, mr1 = NEG, lr0 = 0.0f, lr1 = 0.0f;

        for (int jt = 0; jt <= iq; jt++) {
            asm volatile("cp.async.wait_group 0;");
            __syncthreads();

            // prefetch next tile into the other stage
            if (jt < iq) {
                const int st = (jt + 1) & 1;
                const size_t goff = ((size_t)b * SS + (jt + 1) * 64) * DD;
                const uint4* srcs[4] = {(const uint4*)(g_Kh + goff), (const uint4*)(g_Kl + goff),
                                        (const uint4*)(g_Vh + goff), (const uint4*)(g_Vl + goff)};
                uint32_t sb = uKV + (uint32_t)(st * 4 * T_HALF * 2);
#pragma unroll
                for (int a = 0; a < 4; a++)
#pragma unroll
                    for (int i = 0; i < 2; i++) {
                        int idx = tid + i * 512;
                        int r = idx >> 4, c = idx & 15;
                        cp16(sb + (uint32_t)(a * T_HALF * 2 + (r * 136 + c * 8) * 2),
                             srcs[a] + idx);
                    }
                asm volatile("cp.async.commit_group;");
            }

            const uint32_t sb = uKV + (uint32_t)((jt & 1) * 4 * T_HALF * 2);
            const uint32_t kb = sb + koff0 + loSel;                    // Kh/Kl fused
            const uint32_t vb = sb + 2 * T_HALF * 2 + voff0 + loSel;   // Vh/Vl fused

            // ---- S quarter: 16 rows x 16 keys; c1 = hi*hi, c2 = corrections ----
            float c1[2][4], c2[2][4];
#pragma unroll
            for (int nt = 0; nt < 2; nt++)
#pragma unroll
                for (int k = 0; k < 4; k++) { c1[nt][k] = 0.0f; c2[nt][k] = 0.0f; }

#pragma unroll
            for (int ks = 0; ks < 8; ks++) {
                uint32_t qa[4], ql[4];
                ldsm_x4(qa, uQh + qoff + ks * 32);
                ldsm_x4(ql, uQl + qoff + ks * 32);
#pragma unroll
                for (int nt = 0; nt < 2; nt++) {
                    uint32_t kk[4];   // [0,1]=Khi, [2,3]=Klo
                    ldsm_x4(kk, kb + (uint32_t)(nt * 8 * 136 * 2 + ks * 32));
                    mma_bf16(c1[nt], qa, kk);
                    mma_bf16(c2[nt], qa, kk + 2);
                    mma_bf16(c2[nt], ql, kk);
                }
            }
            float c_[2][4];
#pragma unroll
            for (int nt = 0; nt < 2; nt++)
#pragma unroll
                for (int k = 0; k < 4; k++) c_[nt][k] = c1[nt][k] + c2[nt][k];

            // ---- causal mask (diagonal tile only) ----
            if (jt == iq) {
                const int rl0 = wg * 16 + (lane >> 2);
                const int rl1 = rl0 + 8;
#pragma unroll
                for (int nt = 0; nt < 2; nt++) {
                    int cl = h * 16 + nt * 8 + (lane & 3) * 2;
                    if (cl > rl0) c_[nt][0] = NEG;
                    if (cl + 1 > rl0) c_[nt][1] = NEG;
                    if (cl > rl1) c_[nt][2] = NEG;
                    if (cl + 1 > rl1) c_[nt][3] = NEG;
                }
            }

            // ---- independent online softmax over this key quarter ----
            float mx0 = fmaxf(fmaxf(c_[0][0], c_[0][1]), fmaxf(c_[1][0], c_[1][1]));
            float mx1 = fmaxf(fmaxf(c_[0][2], c_[0][3]), fmaxf(c_[1][2], c_[1][3]));
            mx0 = fmaxf(mx0, __shfl_xor_sync(0xffffffffu, mx0, 1));
            mx0 = fmaxf(mx0, __shfl_xor_sync(0xffffffffu, mx0, 2));
            mx1 = fmaxf(mx1, __shfl_xor_sync(0xffffffffu, mx1, 1));
            mx1 = fmaxf(mx1, __shfl_xor_sync(0xffffffffu, mx1, 2));

            float nm0 = fmaxf(mr0, mx0), nm1 = fmaxf(mr1, mx1);
            float f0 = __expf(mr0 - nm0), f1 = __expf(mr1 - nm1);
            mr0 = nm0; mr1 = nm1;

            float rs0 = 0.0f, rs1 = 0.0f;
#pragma unroll
            for (int nt = 0; nt < 2; nt++) {
                c_[nt][0] = __expf(c_[nt][0] - nm0);
                c_[nt][1] = __expf(c_[nt][1] - nm0);
                c_[nt][2] = __expf(c_[nt][2] - nm1);
                c_[nt][3] = __expf(c_[nt][3] - nm1);
                rs0 += c_[nt][0] + c_[nt][1];
                rs1 += c_[nt][2] + c_[nt][3];
            }
            rs0 += __shfl_xor_sync(0xffffffffu, rs0, 1);
            rs0 += __shfl_xor_sync(0xffffffffu, rs0, 2);
            rs1 += __shfl_xor_sync(0xffffffffu, rs1, 1);
            rs1 += __shfl_xor_sync(0xffffffffu, rs1, 2);
            lr0 = lr0 * f0 + rs0;
            lr1 = lr1 * f1 + rs1;

#pragma unroll
            for (int nd = 0; nd < 16; nd++) {
                o[nd][0] *= f0; o[nd][1] *= f0;
                o[nd][2] *= f1; o[nd][3] *= f1;
            }

            // ---- O += P V over this quarter (16 keys = 1 k-step) ----
            {
                uint32_t ph[4], pl[4];
                split_pack(c_[0][0], c_[0][1], ph[0], pl[0]);
                split_pack(c_[0][2], c_[0][3], ph[1], pl[1]);
                split_pack(c_[1][0], c_[1][1], ph[2], pl[2]);
                split_pack(c_[1][2], c_[1][3], ph[3], pl[3]);
#pragma unroll
                for (int nd = 0; nd < 16; nd++) {
                    uint32_t vv[4];   // [0,1]=Vhi, [2,3]=Vlo
                    ldsm_x4t(vv, vb + (uint32_t)(nd * 16));
                    mma_bf16(o[nd], ph, vv);
                    mma_bf16(o[nd], ph, vv + 2);
                    mma_bf16(o[nd], pl, vv);
                }
            }
        }

        // ---- epilogue: 4-way merge of the key-quarter softmaxes ----
        __syncthreads();   // all compute done before overlaying KV smem
        const int r0 = wg * 16 + (lane >> 2);
        const int cc = (lane & 3) * 2;
        if (h != 0) {
            float* OBh = OB + (h - 1) * 64 * 132;
#pragma unroll
            for (int nd = 0; nd < 16; nd++) {
                *(float2*)(OBh + r0 * 132 + nd * 8 + cc) = make_float2(o[nd][0], o[nd][1]);
                *(float2*)(OBh + (r0 + 8) * 132 + nd * 8 + cc) = make_float2(o[nd][2], o[nd][3]);
            }
            if ((lane & 3) == 0) {
                mB[(h - 1) * 64 + r0] = mr0; mB[(h - 1) * 64 + r0 + 8] = mr1;
                lB[(h - 1) * 64 + r0] = lr0; lB[(h - 1) * 64 + r0 + 8] = lr1;
            }
        }
        __syncthreads();
        if (h == 0) {
            float mb0[3], mb1[3], lb0[3], lb1[3];
            float m0 = mr0, m1 = mr1;
#pragma unroll
            for (int s = 0; s < 3; s++) {
                mb0[s] = mB[s * 64 + r0]; mb1[s] = mB[s * 64 + r0 + 8];
                lb0[s] = lB[s * 64 + r0]; lb1[s] = lB[s * 64 + r0 + 8];
                m0 = fmaxf(m0, mb0[s]); m1 = fmaxf(m1, mb1[s]);
            }
            float fa0 = __expf(mr0 - m0), fa1 = __expf(mr1 - m1);
            float fs0[3], fs1[3];
            float den0 = lr0 * fa0, den1 = lr1 * fa1;
#pragma unroll
            for (int s = 0; s < 3; s++) {
                fs0[s] = __expf(mb0[s] - m0);
                fs1[s] = __expf(mb1[s] - m1);
                den0 += lb0[s] * fs0[s];
                den1 += lb1[s] * fs1[s];
            }
            float inv0 = 1.0f / den0, inv1 = 1.0f / den1;

            const int rg0 = iq * 64 + r0;
            float* o0 = out + ((size_t)b * SS + rg0) * DD + cc;
            float* o1 = o0 + 8 * DD;
#pragma unroll
            for (int nd = 0; nd < 16; nd++) {
                float a0 = o[nd][0] * fa0, a1 = o[nd][1] * fa0;
                float a2 = o[nd][2] * fa1, a3 = o[nd][3] * fa1;
#pragma unroll
                for (int s = 0; s < 3; s++) {
                    float2 ob0 = *(float2*)(OB + s * 64 * 132 + r0 * 132 + nd * 8 + cc);
                    float2 ob1 = *(float2*)(OB + s * 64 * 132 + (r0 + 8) * 132 + nd * 8 + cc);
                    a0 += ob0.x * fs0[s]; a1 += ob0.y * fs0[s];
                    a2 += ob1.x * fs1[s]; a3 += ob1.y * fs1[s];
                }
                *(float2*)(o0 + nd * 8) = make_float2(a0 * inv0, a1 * inv0);
                *(float2*)(o1 + nd * 8) = make_float2(a2 * inv1, a3 * inv1);
            }
        }
    }
}

// ---------------------------------------------------------------------------
extern "C" void kernel_launch(void* const* d_in, const int* in_sizes, int n_in,
                              void* d_out, int out_size) {
    const float* x  = (const float*)d_in[0];
    const float* Wq = (const float*)d_in[1];
    const float* Wk = (const float*)d_in[2];
    const float* Wv = (const float*)d_in[3];
    float* out = (float*)d_out;

    cudaFuncSetAttribute(qkv_kernel, cudaFuncAttributeMaxDynamicSharedMemorySize, QKV_SMEM);
    cudaFuncSetAttribute(attn_kernel, cudaFuncAttributeMaxDynamicSharedMemorySize, ATTN_SMEM);

    qkv_kernel<<<dim3(BB * SS / 128, 3), 256, QKV_SMEM>>>(x, Wq, Wk, Wv);
    attn_kernel<<<dim3(32, BB), 512, ATTN_SMEM>>>(out);
}

// round 6
// speedup vs baseline: 1.1048x; 1.1048x over previous
#include <cuda_runtime.h>
#include <cuda_bf16.h>
#include <cstdint>

// Problem constants
#define BB 4
#define SS 4096
#define DD 128

// bf16 hi/lo split Q,K,V (scale folded into Q). 4 MB each.
__device__ __nv_bfloat16 g_Qh[BB * SS * DD];
__device__ __nv_bfloat16 g_Ql[BB * SS * DD];
__device__ __nv_bfloat16 g_Kh[BB * SS * DD];
__device__ __nv_bfloat16 g_Kl[BB * SS * DD];
__device__ __nv_bfloat16 g_Vh[BB * SS * DD];
__device__ __nv_bfloat16 g_Vl[BB * SS * DD];

// ---------------------------------------------------------------------------
// shared helpers
// ---------------------------------------------------------------------------
__device__ __forceinline__ void ldsm_x4(uint32_t r[4], uint32_t addr) {
    asm volatile("ldmatrix.sync.aligned.m8n8.x4.shared.b16 {%0,%1,%2,%3}, [%4];"
                 : "=r"(r[0]), "=r"(r[1]), "=r"(r[2]), "=r"(r[3]) : "r"(addr));
}
__device__ __forceinline__ void ldsm_x4t(uint32_t r[4], uint32_t addr) {
    asm volatile("ldmatrix.sync.aligned.m8n8.x4.trans.shared.b16 {%0,%1,%2,%3}, [%4];"
                 : "=r"(r[0]), "=r"(r[1]), "=r"(r[2]), "=r"(r[3]) : "r"(addr));
}
__device__ __forceinline__ void mma_bf16(float c[4], const uint32_t a[4],
                                         const uint32_t b[2]) {
    asm volatile(
        "mma.sync.aligned.m16n8k16.row.col.f32.bf16.bf16.f32 "
        "{%0,%1,%2,%3}, {%4,%5,%6,%7}, {%8,%9}, {%0,%1,%2,%3};"
        : "+f"(c[0]), "+f"(c[1]), "+f"(c[2]), "+f"(c[3])
        : "r"(a[0]), "r"(a[1]), "r"(a[2]), "r"(a[3]), "r"(b[0]), "r"(b[1]));
}
// pack (x0,x1) -> bf16x2 hi-part, and residual lo-part
__device__ __forceinline__ void split_pack(float x0, float x1,
                                           uint32_t& hp, uint32_t& lp) {
    asm("cvt.rn.bf16x2.f32 %0, %1, %2;" : "=r"(hp) : "f"(x1), "f"(x0));
    float h0 = __uint_as_float(hp << 16);
    float h1 = __uint_as_float(hp & 0xffff0000u);
    asm("cvt.rn.bf16x2.f32 %0, %1, %2;" : "=r"(lp) : "f"(x1 - h1), "f"(x0 - h0));
}
__device__ __forceinline__ void cp16(uint32_t dst, const void* src) {
    asm volatile("cp.async.cg.shared.global [%0], [%1], 16;" :: "r"(dst), "l"(src));
}

// ---------------------------------------------------------------------------
// Kernel 1: QKV projection via mma.sync bf16 2-way split.
//   y = x @ W^T (Q scaled by 1/sqrt(128)), outputs split bf16 hi/lo.
// Grid (128, 3), 256 threads (8 warps). Warp w owns out rows w*16..+15.
// ---------------------------------------------------------------------------
#define W_HALF (128 * 136)
#define QKV_SMEM (4 * W_HALF * 2)

__global__ __launch_bounds__(256) void qkv_kernel(const float* __restrict__ x,
                                                  const float* __restrict__ Wq,
                                                  const float* __restrict__ Wk,
                                                  const float* __restrict__ Wv) {
    extern __shared__ __nv_bfloat16 qsm[];
    __nv_bfloat16* sXh = qsm;
    __nv_bfloat16* sXl = qsm + W_HALF;
    __nv_bfloat16* sWh = qsm + 2 * W_HALF;
    __nv_bfloat16* sWl = qsm + 3 * W_HALF;

    const uint32_t uB  = (uint32_t)__cvta_generic_to_shared(qsm);
    const uint32_t uXh = uB;
    const uint32_t uXl = uB + W_HALF * 2;
    const uint32_t uWh = uB + 2 * W_HALF * 2;

    const int w = blockIdx.y;
    const float* W = (w == 0) ? Wq : (w == 1) ? Wk : Wv;
    __nv_bfloat16* oh = (w == 0) ? g_Qh : (w == 1) ? g_Kh : g_Vh;
    __nv_bfloat16* ol = (w == 0) ? g_Ql : (w == 1) ? g_Kl : g_Vl;
    const float sc = (w == 0) ? 0.08838834764831845f : 1.0f;

    const int row0 = blockIdx.x * 128;
    const int tid = threadIdx.x;
    const int warp = tid >> 5;
    const int lane = tid & 31;

    // ---- load + convert x tile and W into split bf16 smem ----
    {
        const float4* xg = (const float4*)(x + (size_t)row0 * DD);
        const float4* wg = (const float4*)W;
        for (int t = tid; t < 4096; t += 256) {
            int r = t >> 5;
            int c = (t & 31) * 4;
            float4 xv = xg[t];
            uint32_t h0, l0, h1, l1;
            split_pack(xv.x, xv.y, h0, l0);
            split_pack(xv.z, xv.w, h1, l1);
            *(uint2*)(sXh + r * 136 + c) = make_uint2(h0, h1);
            *(uint2*)(sXl + r * 136 + c) = make_uint2(l0, l1);
            float4 wv = wg[t];
            split_pack(wv.x, wv.y, h0, l0);
            split_pack(wv.z, wv.w, h1, l1);
            *(uint2*)(sWh + r * 136 + c) = make_uint2(h0, h1);
            *(uint2*)(sWl + r * 136 + c) = make_uint2(l0, l1);
        }
    }
    __syncthreads();

    const uint32_t aoff = (uint32_t)(((warp * 16 + (lane & 15)) * 136 +
                                      ((lane >> 4) << 3)) * 2);
    const uint32_t boff = (uint32_t)(((lane & 7) * 136 +
                                      (((lane >> 3) & 1) << 3)) * 2) +
                          ((lane >> 4) ? (uint32_t)(W_HALF * 2) : 0u);

    float o[16][4];
#pragma unroll
    for (int nt = 0; nt < 16; nt++)
#pragma unroll
        for (int k = 0; k < 4; k++) o[nt][k] = 0.0f;

#pragma unroll
    for (int ks = 0; ks < 8; ks++) {
        uint32_t qa[4], ql[4];
        ldsm_x4(qa, uXh + aoff + ks * 32);
        ldsm_x4(ql, uXl + aoff + ks * 32);
#pragma unroll
        for (int nt = 0; nt < 16; nt++) {
            uint32_t kk[4];   // [0,1]=Whi, [2,3]=Wlo
            ldsm_x4(kk, uWh + boff + (uint32_t)(nt * 8 * 136 * 2 + ks * 32));
            mma_bf16(o[nt], qa, kk);
            mma_bf16(o[nt], qa, kk + 2);
            mma_bf16(o[nt], ql, kk);
        }
    }

    const int r0 = row0 + warp * 16 + (lane >> 2);
    const int cc = (lane & 3) * 2;
#pragma unroll
    for (int nt = 0; nt < 16; nt++) {
        uint32_t hp, lp;
        split_pack(o[nt][0] * sc, o[nt][1] * sc, hp, lp);
        *(uint32_t*)(oh + (size_t)r0 * DD + nt * 8 + cc) = hp;
        *(uint32_t*)(ol + (size_t)r0 * DD + nt * 8 + cc) = lp;
        split_pack(o[nt][2] * sc, o[nt][3] * sc, hp, lp);
        *(uint32_t*)(oh + (size_t)(r0 + 8) * DD + nt * 8 + cc) = hp;
        *(uint32_t*)(ol + (size_t)(r0 + 8) * DD + nt * 8 + cc) = lp;
    }
}

// ---------------------------------------------------------------------------
// Kernel 2: causal flash attention, mma.sync bf16 2-way split, 8 warps/CTA
// (R4 layout). Warp w: q-row group wg=w&3 (rows wg*16..+15), key half h=w>>2.
// S-phase accumulators split into c1 (hi*hi) and c2 (corrections): 8
// independent mma chains per warp instead of 4. Independent online softmax
// per key half; merged once per pass via smem. CTA x -> q-tiles {x, 63-x}.
// K/V double-buffered cp.async; hi/lo ldmatrix fused (lanes 16-31 -> lo).
// ---------------------------------------------------------------------------
#define T_HALF 8704
#define ATTN_SMEM (10 * T_HALF * 2)      // 174080 B

__global__ __launch_bounds__(256, 1) void attn_kernel(float* __restrict__ out) {
    extern __shared__ __nv_bfloat16 smh[];

    const uint32_t uB  = (uint32_t)__cvta_generic_to_shared(smh);
    const uint32_t uQh = uB;
    const uint32_t uQl = uB + T_HALF * 2;
    const uint32_t uKV = uB + 2 * T_HALF * 2;      // stage s at uKV + s*4T*2

    __nv_bfloat16* sQh = smh;
    __nv_bfloat16* sQl = smh + T_HALF;
    // epilogue merge buffers overlay KV stage 1
    float* OB = (float*)(smh + 6 * T_HALF);        // [64][132]
    float* mB = OB + 64 * 132;
    float* lB = mB + 64;

    const int b = blockIdx.y;
    const int tid = threadIdx.x;
    const int warp = tid >> 5;
    const int lane = tid & 31;
    const int wg = warp & 3;          // q-row group
    const int h = warp >> 2;          // key half (0: keys 0-31, 1: 32-63)

    const uint32_t qoff = (uint32_t)(((wg * 16 + (lane & 15)) * 136 +
                                      ((lane >> 4) << 3)) * 2);
    const uint32_t koff0 = (uint32_t)(((h * 32 + (lane & 7)) * 136 +
                                       (((lane >> 3) & 1) << 3)) * 2);
    const uint32_t voff0 = (uint32_t)((h * 32 + (lane & 15)) * 136 * 2);
    const uint32_t loSel = (lane >> 4) ? (uint32_t)(T_HALF * 2) : 0u;

    const float NEG = -1e30f;

    for (int pass = 0; pass < 2; pass++) {
        const int iq = pass ? (63 - blockIdx.x) : blockIdx.x;
        __syncthreads();   // previous pass fully done (incl. epilogue reads)

        // ---- load Q tile (hi/lo): 1024 uint4 each ----
        {
            const uint4* QH = (const uint4*)(g_Qh + ((size_t)b * SS + iq * 64) * DD);
            const uint4* QL = (const uint4*)(g_Ql + ((size_t)b * SS + iq * 64) * DD);
#pragma unroll
            for (int i = 0; i < 4; i++) {
                int idx = tid + i * 256;
                int r = idx >> 4, c = idx & 15;
                *(uint4*)(sQh + r * 136 + c * 8) = QH[idx];
                *(uint4*)(sQl + r * 136 + c * 8) = QL[idx];
            }
        }

        // ---- prefetch K/V tile 0 into stage 0 (1024 uint4 per array) ----
        {
            const size_t goff = ((size_t)b * SS) * DD;
            const uint4* srcs[4] = {(const uint4*)(g_Kh + goff), (const uint4*)(g_Kl + goff),
                                    (const uint4*)(g_Vh + goff), (const uint4*)(g_Vl + goff)};
#pragma unroll
            for (int a = 0; a < 4; a++)
#pragma unroll
                for (int i = 0; i < 4; i++) {
                    int idx = tid + i * 256;
                    int r = idx >> 4, c = idx & 15;
                    cp16(uKV + (uint32_t)(a * T_HALF * 2 + (r * 136 + c * 8) * 2),
                         srcs[a] + idx);
                }
            asm volatile("cp.async.commit_group;");
        }

        float o[16][4];
#pragma unroll
        for (int nd = 0; nd < 16; nd++)
#pragma unroll
            for (int k = 0; k < 4; k++) o[nd][k] = 0.0f;
        float mr0 = NEG, mr1 = NEG, lr0 = 0.0f, lr1 = 0.0f;

        for (int jt = 0; jt <= iq; jt++) {
            asm volatile("cp.async.wait_group 0;");
            __syncthreads();

            // prefetch next tile into the other stage
            if (jt < iq) {
                const int st = (jt + 1) & 1;
                const size_t goff = ((size_t)b * SS + (jt + 1) * 64) * DD;
                const uint4* srcs[4] = {(const uint4*)(g_Kh + goff), (const uint4*)(g_Kl + goff),
                                        (const uint4*)(g_Vh + goff), (const uint4*)(g_Vl + goff)};
                uint32_t sb = uKV + (uint32_t)(st * 4 * T_HALF * 2);
#pragma unroll
                for (int a = 0; a < 4; a++)
#pragma unroll
                    for (int i = 0; i < 4; i++) {
                        int idx = tid + i * 256;
                        int r = idx >> 4, c = idx & 15;
                        cp16(sb + (uint32_t)(a * T_HALF * 2 + (r * 136 + c * 8) * 2),
                             srcs[a] + idx);
                    }
                asm volatile("cp.async.commit_group;");
            }

            const uint32_t sb = uKV + (uint32_t)((jt & 1) * 4 * T_HALF * 2);
            const uint32_t kb = sb + koff0 + loSel;                    // Kh/Kl fused
            const uint32_t vb = sb + 2 * T_HALF * 2 + voff0 + loSel;   // Vh/Vl fused

            // ---- S half: 16 rows x 32 keys; c1 = hi*hi, c2 = corrections ----
            float c1[4][4], c2[4][4];
#pragma unroll
            for (int nt = 0; nt < 4; nt++)
#pragma unroll
                for (int k = 0; k < 4; k++) { c1[nt][k] = 0.0f; c2[nt][k] = 0.0f; }

#pragma unroll
            for (int ks = 0; ks < 8; ks++) {
                uint32_t qa[4], ql[4];
                ldsm_x4(qa, uQh + qoff + ks * 32);
                ldsm_x4(ql, uQl + qoff + ks * 32);
#pragma unroll
                for (int nt = 0; nt < 4; nt++) {
                    uint32_t kk[4];   // [0,1]=Khi, [2,3]=Klo
                    ldsm_x4(kk, kb + (uint32_t)(nt * 8 * 136 * 2 + ks * 32));
                    mma_bf16(c1[nt], qa, kk);
                    mma_bf16(c2[nt], qa, kk + 2);
                    mma_bf16(c2[nt], ql, kk);
                }
            }
            float c_[4][4];
#pragma unroll
            for (int nt = 0; nt < 4; nt++)
#pragma unroll
                for (int k = 0; k < 4; k++) c_[nt][k] = c1[nt][k] + c2[nt][k];

            // ---- causal mask (diagonal tile only) ----
            if (jt == iq) {
                const int rl0 = wg * 16 + (lane >> 2);
                const int rl1 = rl0 + 8;
#pragma unroll
                for (int nt = 0; nt < 4; nt++) {
                    int cl = h * 32 + nt * 8 + (lane & 3) * 2;
                    if (cl > rl0) c_[nt][0] = NEG;
                    if (cl + 1 > rl0) c_[nt][1] = NEG;
                    if (cl > rl1) c_[nt][2] = NEG;
                    if (cl + 1 > rl1) c_[nt][3] = NEG;
                }
            }

            // ---- independent online softmax over this key half ----
            float mx0 = NEG, mx1 = NEG;
#pragma unroll
            for (int nt = 0; nt < 4; nt++) {
                mx0 = fmaxf(mx0, fmaxf(c_[nt][0], c_[nt][1]));
                mx1 = fmaxf(mx1, fmaxf(c_[nt][2], c_[nt][3]));
            }
            mx0 = fmaxf(mx0, __shfl_xor_sync(0xffffffffu, mx0, 1));
            mx0 = fmaxf(mx0, __shfl_xor_sync(0xffffffffu, mx0, 2));
            mx1 = fmaxf(mx1, __shfl_xor_sync(0xffffffffu, mx1, 1));
            mx1 = fmaxf(mx1, __shfl_xor_sync(0xffffffffu, mx1, 2));

            float nm0 = fmaxf(mr0, mx0), nm1 = fmaxf(mr1, mx1);
            float f0 = __expf(mr0 - nm0), f1 = __expf(mr1 - nm1);
            mr0 = nm0; mr1 = nm1;

            float rs0 = 0.0f, rs1 = 0.0f;
#pragma unroll
            for (int nt = 0; nt < 4; nt++) {
                c_[nt][0] = __expf(c_[nt][0] - nm0);
                c_[nt][1] = __expf(c_[nt][1] - nm0);
                c_[nt][2] = __expf(c_[nt][2] - nm1);
                c_[nt][3] = __expf(c_[nt][3] - nm1);
                rs0 += c_[nt][0] + c_[nt][1];
                rs1 += c_[nt][2] + c_[nt][3];
            }
            rs0 += __shfl_xor_sync(0xffffffffu, rs0, 1);
            rs0 += __shfl_xor_sync(0xffffffffu, rs0, 2);
            rs1 += __shfl_xor_sync(0xffffffffu, rs1, 1);
            rs1 += __shfl_xor_sync(0xffffffffu, rs1, 2);
            lr0 = lr0 * f0 + rs0;
            lr1 = lr1 * f1 + rs1;

#pragma unroll
            for (int nd = 0; nd < 16; nd++) {
                o[nd][0] *= f0; o[nd][1] *= f0;
                o[nd][2] *= f1; o[nd][3] *= f1;
            }

            // ---- O += P V over this key half (32 keys = 2 k-steps) ----
#pragma unroll
            for (int kp = 0; kp < 2; kp++) {
                uint32_t ph[4], pl[4];
                split_pack(c_[2 * kp][0],     c_[2 * kp][1],     ph[0], pl[0]);
                split_pack(c_[2 * kp][2],     c_[2 * kp][3],     ph[1], pl[1]);
                split_pack(c_[2 * kp + 1][0], c_[2 * kp + 1][1], ph[2], pl[2]);
                split_pack(c_[2 * kp + 1][2], c_[2 * kp + 1][3], ph[3], pl[3]);
#pragma unroll
                for (int nd = 0; nd < 16; nd++) {
                    uint32_t vv[4];   // [0,1]=Vhi, [2,3]=Vlo
                    ldsm_x4t(vv, vb + (uint32_t)(kp * 16 * 136 * 2 + nd * 16));
                    mma_bf16(o[nd], ph, vv);
                    mma_bf16(o[nd], ph, vv + 2);
                    mma_bf16(o[nd], pl, vv);
                }
            }
        }

        // ---- epilogue: merge the two key-half softmaxes, store ----
        __syncthreads();   // all compute done before overlaying stage-1 smem
        const int r0 = wg * 16 + (lane >> 2);
        const int cc = (lane & 3) * 2;
        if (h == 1) {
#pragma unroll
            for (int nd = 0; nd < 16; nd++) {
                *(float2*)(OB + r0 * 132 + nd * 8 + cc) = make_float2(o[nd][0], o[nd][1]);
                *(float2*)(OB + (r0 + 8) * 132 + nd * 8 + cc) = make_float2(o[nd][2], o[nd][3]);
            }
            if ((lane & 3) == 0) {
                mB[r0] = mr0; mB[r0 + 8] = mr1;
                lB[r0] = lr0; lB[r0 + 8] = lr1;
            }
        }
        __syncthreads();
        if (h == 0) {
            float mb0 = mB[r0], mb1 = mB[r0 + 8];
            float lb0 = lB[r0], lb1 = lB[r0 + 8];
            float m0 = fmaxf(mr0, mb0), m1 = fmaxf(mr1, mb1);
            float fa0 = __expf(mr0 - m0), fb0 = __expf(mb0 - m0);
            float fa1 = __expf(mr1 - m1), fb1 = __expf(mb1 - m1);
            float inv0 = 1.0f / (lr0 * fa0 + lb0 * fb0);
            float inv1 = 1.0f / (lr1 * fa1 + lb1 * fb1);

            const int rg0 = iq * 64 + r0;
            float* o0 = out + ((size_t)b * SS + rg0) * DD + cc;
            float* o1 = o0 + 8 * DD;
#pragma unroll
            for (int nd = 0; nd < 16; nd++) {
                float2 ob0 = *(float2*)(OB + r0 * 132 + nd * 8 + cc);
                float2 ob1 = *(float2*)(OB + (r0 + 8) * 132 + nd * 8 + cc);
                *(float2*)(o0 + nd * 8) =
                    make_float2((o[nd][0] * fa0 + ob0.x * fb0) * inv0,
                                (o[nd][1] * fa0 + ob0.y * fb0) * inv0);
                *(float2*)(o1 + nd * 8) =
                    make_float2((o[nd][2] * fa1 + ob1.x * fb1) * inv1,
                                (o[nd][3] * fa1 + ob1.y * fb1) * inv1);
            }
        }
    }
}

// ---------------------------------------------------------------------------
extern "C" void kernel_launch(void* const* d_in, const int* in_sizes, int n_in,
                              void* d_out, int out_size) {
    const float* x  = (const float*)d_in[0];
    const float* Wq = (const float*)d_in[1];
    const float* Wk = (const float*)d_in[2];
    const float* Wv = (const float*)d_in[3];
    float* out = (float*)d_out;

    cudaFuncSetAttribute(qkv_kernel, cudaFuncAttributeMaxDynamicSharedMemorySize, QKV_SMEM);
    cudaFuncSetAttribute(attn_kernel, cudaFuncAttributeMaxDynamicSharedMemorySize, ATTN_SMEM);

    qkv_kernel<<<dim3(BB * SS / 128, 3), 256, QKV_SMEM>>>(x, Wq, Wk, Wv);
    attn_kernel<<<dim3(32, BB), 256, ATTN_SMEM>>>(out);
}